// round 2
// baseline (speedup 1.0000x reference)
#include <cuda_runtime.h>

// out[i, :] = sum_k ppr_scores[i,k] * x[ppr_idx[i,k], :]
// N=100000, K=32, D=128 (fp32). One warp per output row; lane l holds
// (idx[l], score[l]) and broadcasts via shfl. Warp streams neighbor rows as
// coalesced 512B reads (4x128B sectors). x (51MB) is L2-resident; kernel is
// L1tex/LTS throughput bound (~83% both pipes in R1).
//
// R2 changes vs R1:
//  - __launch_bounds__(256, 4): allow ~64 regs so the 8-deep float4 load
//    batch genuinely stays in flight (R1 was squeezed to 32 regs).
//  - __ldg on x (LDG.128.CONSTANT path).
//  - split accumulators to shorten FMA dependency chains.

#define KNEIGH 32
#define DVEC   32   // D/4 float4 per row

__global__ __launch_bounds__(256, 4) void ppr_gather_kernel(
    const float4* __restrict__ x,      // [N, 32] float4
    const int*    __restrict__ idx,    // [N, 32]
    const float*  __restrict__ sc,     // [N, 32]
    float4*       __restrict__ out,    // [N, 32] float4
    int n)
{
    const int warp = (blockIdx.x * blockDim.x + threadIdx.x) >> 5;
    const int lane = threadIdx.x & 31;
    if (warp >= n) return;

    // Lane-held neighbor index/score (K == warpSize).
    const int   my_j = idx[warp * KNEIGH + lane];
    const float my_s = sc[warp * KNEIGH + lane];

    float4 acc0 = make_float4(0.f, 0.f, 0.f, 0.f);
    float4 acc1 = make_float4(0.f, 0.f, 0.f, 0.f);

    #pragma unroll
    for (int k = 0; k < KNEIGH; k += 8) {
        // 8 independent row loads in flight to cover ~250cyc L2 latency.
        float4 v[8];
        float  s[8];
        #pragma unroll
        for (int u = 0; u < 8; ++u) {
            const int jk = __shfl_sync(0xffffffffu, my_j, k + u);
            s[u]         = __shfl_sync(0xffffffffu, my_s, k + u);
            v[u]         = __ldg(&x[(long long)jk * DVEC + lane]);
        }
        #pragma unroll
        for (int u = 0; u < 8; u += 2) {
            acc0.x += s[u] * v[u].x;
            acc0.y += s[u] * v[u].y;
            acc0.z += s[u] * v[u].z;
            acc0.w += s[u] * v[u].w;
            acc1.x += s[u + 1] * v[u + 1].x;
            acc1.y += s[u + 1] * v[u + 1].y;
            acc1.z += s[u + 1] * v[u + 1].z;
            acc1.w += s[u + 1] * v[u + 1].w;
        }
    }

    float4 r;
    r.x = acc0.x + acc1.x;
    r.y = acc0.y + acc1.y;
    r.z = acc0.z + acc1.z;
    r.w = acc0.w + acc1.w;
    out[warp * DVEC + lane] = r;
}

extern "C" void kernel_launch(void* const* d_in, const int* in_sizes, int n_in,
                              void* d_out, int out_size)
{
    const float4* x   = (const float4*)d_in[0];   // [N, D] fp32
    const int*    idx = (const int*)d_in[1];      // [N, K] int32
    const float*  sc  = (const float*)d_in[2];    // [N, K] fp32
    float4*       out = (float4*)d_out;           // [N, D] fp32

    const int n = in_sizes[1] / KNEIGH;           // N rows

    const int warps_per_block = 8;                // 256 threads
    const int blocks = (n + warps_per_block - 1) / warps_per_block;
    ppr_gather_kernel<<<blocks, warps_per_block * 32>>>(x, idx, sc, out, n);
}